// round 10
// baseline (speedup 1.0000x reference)
#include <cuda_runtime.h>
#include <cstdint>

#define B 64
#define K 8
#define V 128000
#define NV4    32000                 // float4 per row
#define SPLIT  5                     // CTAs per row
#define NWARP  8                     // warps per CTA
#define NT     (NWARP * 32)          // 256 threads
#define NCTA   (B * SPLIT)           // 320 CTAs
#define NCHUNK (SPLIT * NWARP)       // 40 warp-chunks per row
#define CHUNK4 (NV4 / NCHUNK)        // 800 float4 per chunk
#define LANE4  (CHUNK4 / 32)         // 25 float4 per lane in refinement

// cross-CTA scratch (no allocations allowed)
__device__ int      g_j[B];
__device__ float    g_u[B];
__device__ int      g_num[B];
__device__ int      g_all[B];
__device__ float    g_csum[B * NCHUNK];
__device__ unsigned g_arrive;        // zero-init; epilogue resets each launch

__global__ void __launch_bounds__(NT)
fused_rs(const int* __restrict__ draft_ids,
         const float* __restrict__ draft_probs,
         const float* __restrict__ target_probs,
         const int* __restrict__ bonus,
         const float* __restrict__ uniforms,
         float* __restrict__ out, int out_size) {
    int bb = blockIdx.x;
    int b = bb / SPLIT, s = bb % SPLIT;
    int tid = threadIdx.x, w = tid >> 5, lane = tid & 31;

    __shared__ int      sh_j, sh_all;
    __shared__ unsigned sh_ticket;

    // ---- Prologue: warp 0 computes the accept chain for row b only ----
    if (w == 0) {
        int k = lane;                  // lanes 0..8 participate in writes
        bool  acc = false;
        float uu  = 0.0f;
        int   id  = 0;
        if (k < K) {
            id = draft_ids[b * K + k];
            uu = uniforms[b * K + k];
            size_t base = (size_t)(b * K + k) * (size_t)V + (size_t)id;
            float p = target_probs[base];
            float q = draft_probs[base];
            float ap = fminf(1.0f, __fdiv_rn(p, fmaxf(q, 1e-10f)));  // bit-exact vs ref
            acc = uu < ap;
        }
        unsigned m = __ballot_sync(0xffffffffu, acc) & 0xFFu;
        int num = __ffs(~m) - 1;       // leading accept run, 0..8
        int j   = (num < K - 1) ? num : (K - 1);
        int all = (num == K) ? 1 : 0;
        float uj = __shfl_sync(0xffffffffu, uu, j);

        if (lane == 0) { sh_j = j; sh_all = all; }

        if (s == 0) {
            if (k < K) {
                // k<num: accepted draft; k>=num: -1 (k==num<K placeholder filled by epilogue)
                out[b * (K + 1) + k] = (k < num) ? (float)id : -1.0f;
            } else if (k == K) {
                out[b * (K + 1) + K] = all ? (float)bonus[b] : -1.0f;
            }
            if (lane == 0) {
                g_j[b]   = j;
                g_u[b]   = uj;
                g_num[b] = num;
                g_all[b] = all;
                if (out_size >= B * (K + 1) + 4 * B) {
                    out[B * (K + 1) + 0 * B + b] = (float)num;
                    out[B * (K + 1) + 1 * B + b] = (float)num;
                    out[B * (K + 1) + 2 * B + b] = (float)(1 - all);
                    out[B * (K + 1) + 3 * B + b] = (float)all;
                }
            }
        }
    }
    __syncthreads();

    // ---- Streaming: fp32 chunk sums of residuals for row j (skip if all) ----
    int j = sh_j;
    if (!sh_all) {
        const float4* tg = reinterpret_cast<const float4*>(
            target_probs + ((size_t)b * K + (size_t)j) * (size_t)V);
        const float4* dr = reinterpret_cast<const float4*>(
            draft_probs + ((size_t)b * K + (size_t)j) * (size_t)V);
        int cb = (s * NWARP + w) * CHUNK4;
        float part = 0.0f;
#pragma unroll 5
        for (int i = lane; i < CHUNK4; i += 32) {
            float4 t4 = tg[cb + i];
            float4 d4 = dr[cb + i];
            part += fmaxf(t4.x - d4.x, 0.0f) + fmaxf(t4.y - d4.y, 0.0f)
                  + fmaxf(t4.z - d4.z, 0.0f) + fmaxf(t4.w - d4.w, 0.0f);
        }
#pragma unroll
        for (int off = 16; off; off >>= 1)
            part += __shfl_down_sync(0xffffffffu, part, off);
        if (lane == 0)
            g_csum[b * NCHUNK + s * NWARP + w] = part;
    }

    // ---- Arrival (threadfence-reduction pattern) ----
    __threadfence();
    __syncthreads();
    if (tid == 0) sh_ticket = atomicAdd(&g_arrive, 1u);
    __syncthreads();
    if (sh_ticket != NCTA - 1) return;

    // ---- Epilogue (last CTA only): one warp per row, rows w, w+8, ... ----
    for (int r = w; r < B; r += NWARP) {
        if (g_all[r]) continue;
        int   jr = g_j[r];
        float ur = g_u[r];
        const float4* tg = reinterpret_cast<const float4*>(
            target_probs + ((size_t)r * K + (size_t)jr) * (size_t)V);
        const float4* dr = reinterpret_cast<const float4*>(
            draft_probs + ((size_t)r * K + (size_t)jr) * (size_t)V);

        int    c = 0, done = 0;
        double t = 0.0, base = 0.0;
        if (lane == 0) {
            double total = 0.0;
            for (int cc = 0; cc < NCHUNK; cc++) total += (double)g_csum[r * NCHUNK + cc];
            if (!(total > 0.0)) {
                done = 1;  // fallback: argmax (never taken on softmax data)
            } else {
                t = (double)ur * total;
                double run = 0.0;
                c = -1;
                for (int cc = 0; cc < NCHUNK; cc++) {
                    double cs = (double)g_csum[r * NCHUNK + cc];
                    if (run + cs > t) { c = cc; break; }
                    run += cs;
                }
                if (c < 0) {  // fp edge: clamp to last chunk
                    c = NCHUNK - 1;
                    run = total - (double)g_csum[r * NCHUNK + NCHUNK - 1];
                }
                base = run;
            }
        }
        done = __shfl_sync(0xffffffffu, done, 0);
        if (done) {
            // full-row argmax of target (first max) — measure-zero path
            float mv = -1.0f; int mi = 0;
            for (int i = lane; i < NV4; i += 32) {
                float4 t4 = tg[i];
                int e = i * 4;
                if (t4.x > mv) { mv = t4.x; mi = e; }
                if (t4.y > mv) { mv = t4.y; mi = e + 1; }
                if (t4.z > mv) { mv = t4.z; mi = e + 2; }
                if (t4.w > mv) { mv = t4.w; mi = e + 3; }
            }
#pragma unroll
            for (int off = 16; off; off >>= 1) {
                float ov = __shfl_down_sync(0xffffffffu, mv, off);
                int   oi = __shfl_down_sync(0xffffffffu, mi, off);
                if (ov > mv || (ov == mv && oi < mi)) { mv = ov; mi = oi; }
            }
            if (lane == 0) out[r * (K + 1) + g_num[r]] = (float)mi;
            continue;
        }
        c    = __shfl_sync(0xffffffffu, c, 0);
        t    = __shfl_sync(0xffffffffu, t, 0);
        base = __shfl_sync(0xffffffffu, base, 0);

        // per-lane sub-chunk sums (25 float4 each, fp32, L2-hot)
        int lb = c * CHUNK4 + lane * LANE4;
        float lsum = 0.0f;
#pragma unroll
        for (int k2 = 0; k2 < LANE4; k2++) {
            float4 t4 = tg[lb + k2];
            float4 d4 = dr[lb + k2];
            lsum += fmaxf(t4.x - d4.x, 0.0f) + fmaxf(t4.y - d4.y, 0.0f)
                  + fmaxf(t4.z - d4.z, 0.0f) + fmaxf(t4.w - d4.w, 0.0f);
        }
        // inclusive warp scan (fp64, 32 adds — trivial)
        double sc = (double)lsum;
#pragma unroll
        for (int off = 1; off < 32; off <<= 1) {
            double o = __shfl_up_sync(0xffffffffu, sc, off);
            if (lane >= off) sc += o;
        }
        unsigned m = __ballot_sync(0xffffffffu, (base + sc) > t);
        int fl = m ? (__ffs(m) - 1) : 31;  // clamp to last lane on fp edge

        if (lane == fl) {
            double run = base + (sc - (double)lsum);   // exclusive prefix
            int idx = (lb + LANE4 - 1) * 4 + 3;        // clamp default
            for (int k2 = 0; k2 < LANE4; k2++) {
                float4 t4 = tg[lb + k2];
                float4 d4 = dr[lb + k2];
                double r0 = (double)fmaxf(t4.x - d4.x, 0.0f);
                double p1 = r0 + (double)fmaxf(t4.y - d4.y, 0.0f);
                double p2 = p1 + (double)fmaxf(t4.z - d4.z, 0.0f);
                double p3 = p2 + (double)fmaxf(t4.w - d4.w, 0.0f);
                int e = (lb + k2) * 4;
                if      (run + r0 > t) { idx = e;     break; }
                else if (run + p1 > t) { idx = e + 1; break; }
                else if (run + p2 > t) { idx = e + 2; break; }
                else if (run + p3 > t) { idx = e + 3; break; }
                run += p3;
            }
            out[r * (K + 1) + g_num[r]] = (float)idx;
        }
    }

    // reset arrival counter for the next graph replay
    __syncthreads();
    if (tid == 0) g_arrive = 0;
}

// ---------------------------------------------------------------------------
extern "C" void kernel_launch(void* const* d_in, const int* in_sizes, int n_in,
                              void* d_out, int out_size) {
    const int*   draft_ids    = (const int*)d_in[0];
    const float* draft_probs  = (const float*)d_in[1];
    const float* target_probs = (const float*)d_in[2];
    const int*   bonus        = (const int*)d_in[3];
    const float* uniforms     = (const float*)d_in[4];
    float* out = (float*)d_out;

    fused_rs<<<NCTA, NT>>>(draft_ids, draft_probs, target_probs, bonus,
                           uniforms, out, out_size);
}

// round 11
// speedup vs baseline: 6.5600x; 6.5600x over previous
#include <cuda_runtime.h>
#include <cstdint>

#define B 64
#define K 8
#define V 128000
#define NV4    32000                 // float4 per row
#define SPLIT  5                     // CTAs per row in kA
#define NWARP  8                     // warps per CTA in kA
#define NT     (NWARP * 32)
#define NCHUNK (SPLIT * NWARP)       // 40 warp-chunks per row
#define CHUNK4 (NV4 / NCHUNK)        // 800 float4 per chunk
#define LANE4  (CHUNK4 / 32)         // 25 float4 per lane
#define BATCH  5                     // 5x5 = 25 per lane

// cross-kernel scratch (no allocations allowed)
__device__ int   g_j[B];
__device__ float g_u[B];
__device__ int   g_num[B];
__device__ int   g_all[B];
__device__ float g_csum[B * NCHUNK];

// ---------------------------------------------------------------------------
// Kernel A: per-CTA accept-chain prologue + lean fp32 streaming pass.
// Streaming uses explicit 5x5 load batching (10 LDG.128 in flight per warp).
// ---------------------------------------------------------------------------
__global__ void __launch_bounds__(NT)
kA_stream(const int* __restrict__ draft_ids,
          const float* __restrict__ draft_probs,
          const float* __restrict__ target_probs,
          const int* __restrict__ bonus,
          const float* __restrict__ uniforms,
          float* __restrict__ out, int out_size) {
    int bb = blockIdx.x;
    int b = bb / SPLIT, s = bb % SPLIT;
    int tid = threadIdx.x, w = tid >> 5, lane = tid & 31;

    __shared__ int sh_j, sh_all;

    // ---- Prologue: warp 0 recomputes the accept chain for row b (16 scattered
    // loads; later CTAs of the same row hit L1/L2). s==0 writes bookkeeping. ----
    if (w == 0) {
        int k = lane;
        bool  acc = false;
        float uu  = 0.0f;
        int   id  = 0;
        if (k < K) {
            id = draft_ids[b * K + k];
            uu = uniforms[b * K + k];
            size_t base = (size_t)(b * K + k) * (size_t)V + (size_t)id;
            float p = target_probs[base];
            float q = draft_probs[base];
            float ap = fminf(1.0f, __fdiv_rn(p, fmaxf(q, 1e-10f)));  // bit-exact vs ref
            acc = uu < ap;
        }
        unsigned m = __ballot_sync(0xffffffffu, acc) & 0xFFu;
        int num = __ffs(~m) - 1;       // leading accept run, 0..8
        int j   = (num < K - 1) ? num : (K - 1);
        int all = (num == K) ? 1 : 0;
        float uj = __shfl_sync(0xffffffffu, uu, j);

        if (lane == 0) { sh_j = j; sh_all = all; }

        if (s == 0) {
            if (k < K) {
                out[b * (K + 1) + k] = (k < num) ? (float)id : -1.0f;
            } else if (k == K) {
                out[b * (K + 1) + K] = all ? (float)bonus[b] : -1.0f;
            }
            if (lane == 0) {
                g_j[b]   = j;
                g_u[b]   = uj;
                g_num[b] = num;
                g_all[b] = all;
                if (out_size >= B * (K + 1) + 4 * B) {
                    out[B * (K + 1) + 0 * B + b] = (float)num;
                    out[B * (K + 1) + 1 * B + b] = (float)num;
                    out[B * (K + 1) + 2 * B + b] = (float)(1 - all);
                    out[B * (K + 1) + 3 * B + b] = (float)all;
                }
            }
        }
    }
    __syncthreads();

    if (sh_all) return;
    int j = sh_j;

    const float4* tg = reinterpret_cast<const float4*>(
        target_probs + ((size_t)b * K + (size_t)j) * (size_t)V);
    const float4* dr = reinterpret_cast<const float4*>(
        draft_probs + ((size_t)b * K + (size_t)j) * (size_t)V);
    int cb = (s * NWARP + w) * CHUNK4;

    // ---- Streaming: 25 float4-pairs per lane in 5 batches of 5.
    // All 10 loads of a batch are issued before any accumulation. ----
    float part = 0.0f;
#pragma unroll
    for (int ii = 0; ii < BATCH; ii++) {
        float4 ta[BATCH], da[BATCH];
#pragma unroll
        for (int jj = 0; jj < BATCH; jj++) {
            int idx = cb + (ii * BATCH + jj) * 32 + lane;
            ta[jj] = __ldg(&tg[idx]);
            da[jj] = __ldg(&dr[idx]);
        }
#pragma unroll
        for (int jj = 0; jj < BATCH; jj++) {
            part += fmaxf(ta[jj].x - da[jj].x, 0.0f)
                  + fmaxf(ta[jj].y - da[jj].y, 0.0f)
                  + fmaxf(ta[jj].z - da[jj].z, 0.0f)
                  + fmaxf(ta[jj].w - da[jj].w, 0.0f);
        }
    }
#pragma unroll
    for (int off = 16; off; off >>= 1)
        part += __shfl_down_sync(0xffffffffu, part, off);
    if (lane == 0)
        g_csum[b * NCHUNK + s * NWARP + w] = part;
}

// ---------------------------------------------------------------------------
// Kernel B: one warp per row. Combine 40 chunk sums (fp64) -> crossing chunk;
// fp32 lane sums + fp64 scan; crossing lane walks its 25 float4 (L2-hot).
// ---------------------------------------------------------------------------
__global__ void __launch_bounds__(32)
kB_pick(const float* __restrict__ draft_probs,
        const float* __restrict__ target_probs,
        float* __restrict__ out) {
    int b = blockIdx.x;
    if (g_all[b]) return;

    int lane = threadIdx.x;
    int j = g_j[b];
    float u = g_u[b];
    const float4* tg = reinterpret_cast<const float4*>(
        target_probs + ((size_t)b * K + (size_t)j) * (size_t)V);
    const float4* dr = reinterpret_cast<const float4*>(
        draft_probs + ((size_t)b * K + (size_t)j) * (size_t)V);

    int    c = 0, done = 0;
    double t = 0.0, base = 0.0;
    if (lane == 0) {
        double total = 0.0;
        for (int cc = 0; cc < NCHUNK; cc++) total += (double)g_csum[b * NCHUNK + cc];
        if (!(total > 0.0)) {
            done = 1;  // fallback: full-row argmax (never taken on softmax data)
        } else {
            t = (double)u * total;
            double run = 0.0;
            c = -1;
            for (int cc = 0; cc < NCHUNK; cc++) {
                double cs = (double)g_csum[b * NCHUNK + cc];
                if (run + cs > t) { c = cc; break; }
                run += cs;
            }
            if (c < 0) {  // fp edge: clamp to last chunk
                c = NCHUNK - 1;
                run = total - (double)g_csum[b * NCHUNK + NCHUNK - 1];
            }
            base = run;
        }
    }
    done = __shfl_sync(0xffffffffu, done, 0);
    if (done) {
        float mv = -1.0f; int mi = 0;
        for (int i = lane; i < NV4; i += 32) {
            float4 t4 = tg[i];
            int e = i * 4;
            if (t4.x > mv) { mv = t4.x; mi = e; }
            if (t4.y > mv) { mv = t4.y; mi = e + 1; }
            if (t4.z > mv) { mv = t4.z; mi = e + 2; }
            if (t4.w > mv) { mv = t4.w; mi = e + 3; }
        }
#pragma unroll
        for (int off = 16; off; off >>= 1) {
            float ov = __shfl_down_sync(0xffffffffu, mv, off);
            int   oi = __shfl_down_sync(0xffffffffu, mi, off);
            if (ov > mv || (ov == mv && oi < mi)) { mv = ov; mi = oi; }
        }
        if (lane == 0) out[b * (K + 1) + g_num[b]] = (float)mi;
        return;
    }
    c    = __shfl_sync(0xffffffffu, c, 0);
    t    = __shfl_sync(0xffffffffu, t, 0);
    base = __shfl_sync(0xffffffffu, base, 0);

    // per-lane contiguous sub-chunk sums (25 float4 each, fp32, L2-hot)
    int lb = c * CHUNK4 + lane * LANE4;
    float lsum = 0.0f;
#pragma unroll
    for (int k2 = 0; k2 < LANE4; k2++) {
        float4 t4 = tg[lb + k2];
        float4 d4 = dr[lb + k2];
        lsum += fmaxf(t4.x - d4.x, 0.0f) + fmaxf(t4.y - d4.y, 0.0f)
              + fmaxf(t4.z - d4.z, 0.0f) + fmaxf(t4.w - d4.w, 0.0f);
    }
    // inclusive warp scan over lane sums (fp64, 32 adds — trivial)
    double sc = (double)lsum;
#pragma unroll
    for (int off = 1; off < 32; off <<= 1) {
        double o = __shfl_up_sync(0xffffffffu, sc, off);
        if (lane >= off) sc += o;
    }
    unsigned m = __ballot_sync(0xffffffffu, (base + sc) > t);
    int fl = m ? (__ffs(m) - 1) : 31;  // clamp to last lane on fp edge

    if (lane == fl) {
        double run = base + (sc - (double)lsum);   // exclusive prefix
        int idx = (lb + LANE4 - 1) * 4 + 3;        // clamp default
        for (int k2 = 0; k2 < LANE4; k2++) {
            float4 t4 = tg[lb + k2];
            float4 d4 = dr[lb + k2];
            double r0 = (double)fmaxf(t4.x - d4.x, 0.0f);
            double p1 = r0 + (double)fmaxf(t4.y - d4.y, 0.0f);
            double p2 = p1 + (double)fmaxf(t4.z - d4.z, 0.0f);
            double p3 = p2 + (double)fmaxf(t4.w - d4.w, 0.0f);
            int e = (lb + k2) * 4;
            if      (run + r0 > t) { idx = e;     break; }
            else if (run + p1 > t) { idx = e + 1; break; }
            else if (run + p2 > t) { idx = e + 2; break; }
            else if (run + p3 > t) { idx = e + 3; break; }
            run += p3;
        }
        out[b * (K + 1) + g_num[b]] = (float)idx;
    }
}

// ---------------------------------------------------------------------------
extern "C" void kernel_launch(void* const* d_in, const int* in_sizes, int n_in,
                              void* d_out, int out_size) {
    const int*   draft_ids    = (const int*)d_in[0];
    const float* draft_probs  = (const float*)d_in[1];
    const float* target_probs = (const float*)d_in[2];
    const int*   bonus        = (const int*)d_in[3];
    const float* uniforms     = (const float*)d_in[4];
    float* out = (float*)d_out;

    kA_stream<<<B * SPLIT, NT>>>(draft_ids, draft_probs, target_probs, bonus,
                                 uniforms, out, out_size);
    kB_pick<<<B, 32>>>(draft_probs, target_probs, out);
}

// round 12
// speedup vs baseline: 11.8254x; 1.8027x over previous
#include <cuda_runtime.h>
#include <cstdint>

#define B 64
#define K 8
#define V 128000
#define NV4    32000                 // float4 per row
#define SPLIT  5                     // CTAs per row in kA
#define NWARP  8                     // warps per CTA in kA
#define NT     (NWARP * 32)
#define NCHUNK (SPLIT * NWARP)       // 40 warp-chunks per row
#define CHUNK4 (NV4 / NCHUNK)        // 800 float4 per chunk
#define LANE4  (CHUNK4 / 32)         // 25 float4 per lane
#define BATCH  5                     // 5x5 = 25 per lane

// cross-kernel scratch (no allocations allowed)
__device__ int   g_j[B];
__device__ float g_u[B];
__device__ int   g_num[B];
__device__ int   g_all[B];
__device__ float g_csum[B * NCHUNK];

// ---------------------------------------------------------------------------
// Kernel A: per-CTA accept-chain prologue + lean fp32 streaming pass.
// (unchanged from R11 — measured ~7us, near DRAM roofline for this shape)
// ---------------------------------------------------------------------------
__global__ void __launch_bounds__(NT)
kA_stream(const int* __restrict__ draft_ids,
          const float* __restrict__ draft_probs,
          const float* __restrict__ target_probs,
          const int* __restrict__ bonus,
          const float* __restrict__ uniforms,
          float* __restrict__ out, int out_size) {
    int bb = blockIdx.x;
    int b = bb / SPLIT, s = bb % SPLIT;
    int tid = threadIdx.x, w = tid >> 5, lane = tid & 31;

    __shared__ int sh_j, sh_all;

    if (w == 0) {
        int k = lane;
        bool  acc = false;
        float uu  = 0.0f;
        int   id  = 0;
        if (k < K) {
            id = draft_ids[b * K + k];
            uu = uniforms[b * K + k];
            size_t base = (size_t)(b * K + k) * (size_t)V + (size_t)id;
            float p = target_probs[base];
            float q = draft_probs[base];
            float ap = fminf(1.0f, __fdiv_rn(p, fmaxf(q, 1e-10f)));  // bit-exact vs ref
            acc = uu < ap;
        }
        unsigned m = __ballot_sync(0xffffffffu, acc) & 0xFFu;
        int num = __ffs(~m) - 1;
        int j   = (num < K - 1) ? num : (K - 1);
        int all = (num == K) ? 1 : 0;
        float uj = __shfl_sync(0xffffffffu, uu, j);

        if (lane == 0) { sh_j = j; sh_all = all; }

        if (s == 0) {
            if (k < K) {
                out[b * (K + 1) + k] = (k < num) ? (float)id : -1.0f;
            } else if (k == K) {
                out[b * (K + 1) + K] = all ? (float)bonus[b] : -1.0f;
            }
            if (lane == 0) {
                g_j[b]   = j;
                g_u[b]   = uj;
                g_num[b] = num;
                g_all[b] = all;
                if (out_size >= B * (K + 1) + 4 * B) {
                    out[B * (K + 1) + 0 * B + b] = (float)num;
                    out[B * (K + 1) + 1 * B + b] = (float)num;
                    out[B * (K + 1) + 2 * B + b] = (float)(1 - all);
                    out[B * (K + 1) + 3 * B + b] = (float)all;
                }
            }
        }
    }
    __syncthreads();

    if (sh_all) return;
    int j = sh_j;

    const float4* tg = reinterpret_cast<const float4*>(
        target_probs + ((size_t)b * K + (size_t)j) * (size_t)V);
    const float4* dr = reinterpret_cast<const float4*>(
        draft_probs + ((size_t)b * K + (size_t)j) * (size_t)V);
    int cb = (s * NWARP + w) * CHUNK4;

    float part = 0.0f;
#pragma unroll
    for (int ii = 0; ii < BATCH; ii++) {
        float4 ta[BATCH], da[BATCH];
#pragma unroll
        for (int jj = 0; jj < BATCH; jj++) {
            int idx = cb + (ii * BATCH + jj) * 32 + lane;
            ta[jj] = __ldg(&tg[idx]);
            da[jj] = __ldg(&dr[idx]);
        }
#pragma unroll
        for (int jj = 0; jj < BATCH; jj++) {
            part += fmaxf(ta[jj].x - da[jj].x, 0.0f)
                  + fmaxf(ta[jj].y - da[jj].y, 0.0f)
                  + fmaxf(ta[jj].z - da[jj].z, 0.0f)
                  + fmaxf(ta[jj].w - da[jj].w, 0.0f);
        }
    }
#pragma unroll
    for (int off = 16; off; off >>= 1)
        part += __shfl_down_sync(0xffffffffu, part, off);
    if (lane == 0)
        g_csum[b * NCHUNK + s * NWARP + w] = part;
}

// inclusive fp64 warp scan
__device__ __forceinline__ double wscan(double v, int lane) {
#pragma unroll
    for (int off = 1; off < 32; off <<= 1) {
        double o = __shfl_up_sync(0xffffffffu, v, off);
        if (lane >= off) v += o;
    }
    return v;
}

// ---------------------------------------------------------------------------
// Kernel B: one warp per row, all-lane-parallel at every level (R11's 23us
// came from serial dependent-load chains in lane 0 / the crossing lane).
// ---------------------------------------------------------------------------
__global__ void __launch_bounds__(32)
kB_pick(const float* __restrict__ draft_probs,
        const float* __restrict__ target_probs,
        float* __restrict__ out) {
    int b = blockIdx.x;
    if (g_all[b]) return;

    int lane = threadIdx.x;
    int j = g_j[b];
    float u = g_u[b];
    const float4* tg = reinterpret_cast<const float4*>(
        target_probs + ((size_t)b * K + (size_t)j) * (size_t)V);
    const float4* dr = reinterpret_cast<const float4*>(
        draft_probs + ((size_t)b * K + (size_t)j) * (size_t)V);

    // ---- Level 1: parallel load + scan of the 40 chunk sums ----
    double v1 = (double)g_csum[b * NCHUNK + lane];                 // chunks 0..31
    double v2 = (lane < NCHUNK - 32)
              ? (double)g_csum[b * NCHUNK + 32 + lane] : 0.0;      // chunks 32..39
    double s1 = wscan(v1, lane);
    double s2 = wscan(v2, lane);
    double sum1   = __shfl_sync(0xffffffffu, s1, 31);
    double total2 = __shfl_sync(0xffffffffu, s2, 31);
    double total  = sum1 + total2;

    if (!(total > 0.0)) {
        // fallback: full-row argmax of target (measure-zero on softmax data)
        float mv = -1.0f; int mi = 0;
        for (int i = lane; i < NV4; i += 32) {
            float4 t4 = tg[i];
            int e = i * 4;
            if (t4.x > mv) { mv = t4.x; mi = e; }
            if (t4.y > mv) { mv = t4.y; mi = e + 1; }
            if (t4.z > mv) { mv = t4.z; mi = e + 2; }
            if (t4.w > mv) { mv = t4.w; mi = e + 3; }
        }
#pragma unroll
        for (int off = 16; off; off >>= 1) {
            float ov = __shfl_down_sync(0xffffffffu, mv, off);
            int   oi = __shfl_down_sync(0xffffffffu, mi, off);
            if (ov > mv || (ov == mv && oi < mi)) { mv = ov; mi = oi; }
        }
        if (lane == 0) out[b * (K + 1) + g_num[b]] = (float)mi;
        return;
    }
    double t = (double)u * total;

    unsigned m1 = __ballot_sync(0xffffffffu, s1 > t);
    unsigned m2 = __ballot_sync(0xffffffffu, (lane < NCHUNK - 32) && (sum1 + s2 > t));
    int c; double base;
    if (m1) {
        c = __ffs(m1) - 1;
        base = __shfl_sync(0xffffffffu, s1 - v1, c);
    } else if (m2) {
        int c2 = __ffs(m2) - 1;
        c = 32 + c2;
        base = sum1 + __shfl_sync(0xffffffffu, s2 - v2, c2);
    } else {  // fp edge: clamp to last chunk
        c = NCHUNK - 1;
        base = total - __shfl_sync(0xffffffffu, v2, NCHUNK - 1 - 32);
    }

    // ---- Level 2: per-lane segment sums inside chunk c (25 float4 each) ----
    int lb = c * CHUNK4 + lane * LANE4;
    float lsum = 0.0f;
#pragma unroll
    for (int k2 = 0; k2 < LANE4; k2++) {
        float4 t4 = __ldg(&tg[lb + k2]);
        float4 d4 = __ldg(&dr[lb + k2]);
        lsum += fmaxf(t4.x - d4.x, 0.0f) + fmaxf(t4.y - d4.y, 0.0f)
              + fmaxf(t4.z - d4.z, 0.0f) + fmaxf(t4.w - d4.w, 0.0f);
    }
    double sc = wscan((double)lsum, lane);
    unsigned mm = __ballot_sync(0xffffffffu, (base + sc) > t);
    int fl = mm ? (__ffs(mm) - 1) : 31;                // clamp on fp edge
    double run0 = base + __shfl_sync(0xffffffffu, sc - (double)lsum, fl);

    // ---- Level 3: element-level, parallel over the crossing segment.
    // Lanes 0..24 each take one float4 of lane fl's segment (L1-hot). ----
    int sb = c * CHUNK4 + fl * LANE4;
    double r0 = 0.0, p1 = 0.0, p2 = 0.0, p3 = 0.0;
    if (lane < LANE4) {
        float4 t4 = tg[sb + lane];
        float4 d4 = dr[sb + lane];
        r0 = (double)fmaxf(t4.x - d4.x, 0.0f);
        p1 = r0 + (double)fmaxf(t4.y - d4.y, 0.0f);
        p2 = p1 + (double)fmaxf(t4.z - d4.z, 0.0f);
        p3 = p2 + (double)fmaxf(t4.w - d4.w, 0.0f);
    }
    double es = wscan(p3, lane);
    unsigned me = __ballot_sync(0xffffffffu, (lane < LANE4) && (run0 + es > t));
    int fe = me ? (__ffs(me) - 1) : (LANE4 - 1);       // clamp on fp edge

    if (lane == fe) {
        double run = run0 + (es - p3);                 // exclusive prefix
        int sub = 3;                                   // clamp default
        if      (run + r0 > t) sub = 0;
        else if (run + p1 > t) sub = 1;
        else if (run + p2 > t) sub = 2;
        out[b * (K + 1) + g_num[b]] = (float)((sb + lane) * 4 + sub);
    }
}

// ---------------------------------------------------------------------------
extern "C" void kernel_launch(void* const* d_in, const int* in_sizes, int n_in,
                              void* d_out, int out_size) {
    const int*   draft_ids    = (const int*)d_in[0];
    const float* draft_probs  = (const float*)d_in[1];
    const float* target_probs = (const float*)d_in[2];
    const int*   bonus        = (const int*)d_in[3];
    const float* uniforms     = (const float*)d_in[4];
    float* out = (float*)d_out;

    kA_stream<<<B * SPLIT, NT>>>(draft_ids, draft_probs, target_probs, bonus,
                                 uniforms, out, out_size);
    kB_pick<<<B, 32>>>(draft_probs, target_probs, out);
}